// round 12
// baseline (speedup 1.0000x reference)
#include <cuda_runtime.h>
#include <cuda_bf16.h>
#include <math.h>

// Problem constants (fixed by the reference setup)
#define BB 4
#define CC 32
#define NCP 16          // channel pairs
#define PP 262144       // 512*512 pixels per image
#define NI 100          // n_instances
#define CHUNK 2048      // pixels per block
#define TPB 512
#define NCOPY 8         // bank-sliced histogram copies
#define CPB 128         // chunks (blocks) per batch image

// Scratch (no device allocation allowed -> __device__ globals).
// Zero at module load; K3's ticket block re-zeros accumulators/counters after
// each run so every graph replay starts clean. g_means/g_invc/g_dist/g_reg
// are overwritten (not accumulated) every run.
__device__ float g_sums[BB*CC*NI];   // [b][c*NI+k]
__device__ int   g_counts[BB*NI];
__device__ float g_means[BB*CC*NI];
__device__ float g_invc[BB*NI];
__device__ float g_var[BB];
__device__ float g_dist[BB];
__device__ float g_reg[BB];
__device__ unsigned int g_ta;   // K1 p1-completion ticket
__device__ unsigned int g_tb;   // K2 p1-completion ticket
__device__ unsigned int g_tc;   // K3 completion ticket

// ---------------- role bodies (shared by the three kernels) ----------------

// Phase-1 histogram for (batch b, chunk): bf16x2 atomics, 8-way bank-sliced.
__device__ __forceinline__ void run_p1(const float* __restrict__ in,
                                       const int* __restrict__ tgt,
                                       int b, int chunk,
                                       __nv_bfloat162* ssum, int* scnt, int t) {
    int p0  = chunk * CHUNK;
    int cpy = t & (NCOPY-1);

    __nv_bfloat162 z2 = __nv_bfloat162(__float2bfloat16(0.f), __float2bfloat16(0.f));
    for (int i = t; i < NCP*NI*NCOPY; i += TPB) ssum[i] = z2;
    for (int i = t; i < NI;           i += TPB) scnt[i] = 0;
    __syncthreads();

    const int4* tg = (const int4*)(tgt + (size_t)b * PP + p0);
    int4 lv = tg[t];
    int lbl[4] = {lv.x, lv.y, lv.z, lv.w};
#pragma unroll
    for (int k = 0; k < 4; k++) atomicAdd(&scnt[lbl[k]], 1);

    int s0 = lbl[0]*NCOPY + cpy;
    int s1 = lbl[1]*NCOPY + cpy;
    int s2 = lbl[2]*NCOPY + cpy;
    int s3 = lbl[3]*NCOPY + cpy;

    const float* base = in + (size_t)b * CC * PP + p0;
#pragma unroll 2
    for (int cp = 0; cp < NCP; cp++) {
        const float4* pc0 = (const float4*)(base + (size_t)(2*cp)   * PP);
        const float4* pc1 = (const float4*)(base + (size_t)(2*cp+1) * PP);
        float4 v0 = pc0[t];
        float4 v1 = pc1[t];
        __nv_bfloat162 p0v = __floats2bfloat162_rn(v0.x, v1.x);
        __nv_bfloat162 p1v = __floats2bfloat162_rn(v0.y, v1.y);
        __nv_bfloat162 p2v = __floats2bfloat162_rn(v0.z, v1.z);
        __nv_bfloat162 p3v = __floats2bfloat162_rn(v0.w, v1.w);
        int cb = cp*NI*NCOPY;
        atomicAdd(&ssum[cb + s0], p0v);
        atomicAdd(&ssum[cb + s1], p1v);
        atomicAdd(&ssum[cb + s2], p2v);
        atomicAdd(&ssum[cb + s3], p3v);
    }
    __syncthreads();

    float* gs = g_sums + (size_t)b * CC * NI;
    for (int i = t; i < NCP*NI; i += TPB) {
        int cp = i / NI;
        int k  = i - cp * NI;
        float sx = 0.f, sy = 0.f;
#pragma unroll
        for (int c = 0; c < NCOPY; c++) {
            __nv_bfloat162 v = ssum[i*NCOPY + c];
            sx += __bfloat162float(v.x);
            sy += __bfloat162float(v.y);
        }
        atomicAdd(&gs[(2*cp)   * NI + k], sx);
        atomicAdd(&gs[(2*cp+1) * NI + k], sy);
    }
    int* gc = g_counts + b * NI;
    for (int i = t; i < NI; i += TPB) atomicAdd(&gc[i], scnt[i]);
}

// Means + inv-counts for batches [b0, b0+1] (cheap block-wide tail).
__device__ __forceinline__ void run_means(int b0, int t) {
    for (int i = t; i < 2*CC*NI; i += TPB) {
        int bb = b0 + i / (CC*NI);
        int ck = i % (CC*NI);
        int k  = ck % NI;
        int cnt = g_counts[bb*NI + k];
        g_means[(size_t)bb*CC*NI + ck] = (cnt > 0) ? g_sums[(size_t)bb*CC*NI + ck] / (float)cnt : 0.f;
    }
    for (int i = t; i < 2*NI; i += TPB) {
        int bb = b0 + i / NI;
        int k  = i % NI;
        int cnt = g_counts[bb*NI + k];
        g_invc[bb*NI + k] = (cnt > 0) ? 1.f / (float)cnt : 0.f;
    }
}

// Variance term for (batch b, chunk). Reads precomputed g_means/g_invc.
__device__ __forceinline__ void run_var(const float* __restrict__ in,
                                        const int* __restrict__ tgt,
                                        int b, int chunk,
                                        float* sh, float* sred, int t) {
    float* smean = sh;             // [c*NI+k], 3200
    float* sinv  = sh + CC*NI;     // [k], 100
    int p0 = chunk * CHUNK;

    for (int i = t; i < CC*NI; i += TPB) smean[i] = g_means[(size_t)b*CC*NI + i];
    for (int i = t; i < NI;    i += TPB) sinv[i]  = g_invc[b*NI + i];
    __syncthreads();

    const int4* tg = (const int4*)(tgt + (size_t)b * PP + p0);
    int4 lv = tg[t];
    int lbl[4] = {lv.x, lv.y, lv.z, lv.w};

    float acc[4] = {0.f, 0.f, 0.f, 0.f};
    const float* base = in + (size_t)b * CC * PP + p0;
#pragma unroll 4
    for (int c = 0; c < CC; c++) {
        const float4* pc = (const float4*)(base + (size_t)c * PP);
        float4 v = pc[t];
        float d0 = v.x - smean[c*NI + lbl[0]];
        float d1 = v.y - smean[c*NI + lbl[1]];
        float d2 = v.z - smean[c*NI + lbl[2]];
        float d3 = v.w - smean[c*NI + lbl[3]];
        acc[0] = fmaf(d0, d0, acc[0]);
        acc[1] = fmaf(d1, d1, acc[1]);
        acc[2] = fmaf(d2, d2, acc[2]);
        acc[3] = fmaf(d3, d3, acc[3]);
    }

    float local = 0.f;
#pragma unroll
    for (int k = 0; k < 4; k++) {
        float n = sqrtf(acc[k]);
        float h = fmaxf(n - 0.75f, 0.f);   // DELTA_VAR
        local += h * h * sinv[lbl[k]];
    }
#pragma unroll
    for (int o = 16; o > 0; o >>= 1) local += __shfl_down_sync(0xffffffffu, local, o);
    if ((t & 31) == 0) sred[t >> 5] = local;
    __syncthreads();
    if (t < 32) {
        float v = (t < TPB/32) ? sred[t] : 0.f;
#pragma unroll
        for (int o = 16; o > 0; o >>= 1) v += __shfl_down_sync(0xffffffffu, v, o);
        if (t == 0) atomicAdd(&g_var[b], v);
    }
}

// Distance + reg terms for one batch (smem-only, keeps regs low).
__device__ __forceinline__ void run_dist(int b, float* sh, float* sred, int t) {
    float* sm = sh;                // [k*33+c] padded
    const float* gm = g_means + (size_t)b * CC * NI;   // [c*NI+k]
    for (int i = t; i < CC*NI; i += TPB) {
        int c = i / NI;
        int k = i - c * NI;
        sm[k*33 + c] = gm[i];
    }
    if (t == 0) sred[16] = 0.f;
    __syncthreads();

    if (t < NI) {
        float s = 0.f;
#pragma unroll
        for (int c = 0; c < CC; c++) { float m = sm[t*33 + c]; s = fmaf(m, m, s); }
        atomicAdd(&sred[16], sqrtf(s));
    }

    float local = 0.f;
    for (int idx = t; idx < NI*NI; idx += TPB) {
        int i = idx / NI;
        int j = idx - i * NI;
        if (i != j) {
            float d2 = 0.f;
#pragma unroll
            for (int c = 0; c < CC; c++) {
                float d = sm[i*33 + c] - sm[j*33 + c];
                d2 = fmaf(d, d, d2);
            }
            float d = (d2 > 0.f) ? sqrtf(d2) : 1.f;   // jnp.where(d2>0, d2, 1)
            float h = fmaxf(4.f - d, 0.f);            // 2*DELTA_DIST
            local += h * h;
        }
    }
#pragma unroll
    for (int o = 16; o > 0; o >>= 1) local += __shfl_down_sync(0xffffffffu, local, o);
    if ((t & 31) == 0) sred[t >> 5] = local;
    __syncthreads();
    if (t < 32) {
        float v = (t < TPB/32) ? sred[t] : 0.f;
#pragma unroll
        for (int o = 16; o > 0; o >>= 1) v += __shfl_down_sync(0xffffffffu, v, o);
        if (t == 0) {
            g_dist[b] = v;
            g_reg[b]  = sred[16];
        }
    }
}

// ---------------- K1: pass1 for batches 0,1 (+ means tail) ----------------
__global__ __launch_bounds__(TPB) void k1(const float* __restrict__ in,
                                          const int* __restrict__ tgt) {
    __shared__ __align__(16) __nv_bfloat162 ssum[NCP*NI*NCOPY];  // 51.2KB
    __shared__ int scnt[NI];
    __shared__ bool s_last;
    int t = threadIdx.x;

    run_p1(in, tgt, blockIdx.x >> 7, blockIdx.x & 127, ssum, scnt, t);

    __syncthreads();
    if (t == 0) {
        __threadfence();
        s_last = (atomicAdd(&g_ta, 1u) == 2*CPB - 1);
    }
    __syncthreads();
    if (s_last) run_means(0, t);
}

// ---- K2: pass1 b2,b3 (even bids) interleaved with variance b0,b1 (odd) ----
// + 2 distance blocks for b0,b1. p1 tail computes means for b2,b3.
__global__ __launch_bounds__(TPB) void k2(const float* __restrict__ in,
                                          const int* __restrict__ tgt) {
    __shared__ __align__(16) __nv_bfloat162 ssum[NCP*NI*NCOPY];
    __shared__ int scnt[NI];
    __shared__ float sred[24];
    __shared__ bool s_last;
    int blk = blockIdx.x;
    int t   = threadIdx.x;

    if (blk < 2*2*CPB) {                 // 512 mixed-role blocks
        int i = blk >> 1;                // 0..255
        if ((blk & 1) == 0) {
            run_p1(in, tgt, 2 + (i >> 7), i & 127, ssum, scnt, t);
            __syncthreads();
            if (t == 0) {
                __threadfence();
                s_last = (atomicAdd(&g_tb, 1u) == 2*CPB - 1);
            }
            __syncthreads();
            if (s_last) run_means(2, t);
        } else {
            run_var(in, tgt, i >> 7, i & 127, (float*)ssum, sred, t);
        }
    } else {
        run_dist(blk - 2*2*CPB, (float*)ssum, sred, t);   // b = 0 or 1
    }
}

// -------- K3: variance b2,b3 + distance b2,b3 + final combine + cleanup -----
#define K3BLK (2*CPB + 2)   // 258
__global__ __launch_bounds__(TPB) void k3(const float* __restrict__ in,
                                          const int* __restrict__ tgt,
                                          float* __restrict__ out) {
    __shared__ __align__(16) float sh[NI*33 + 32];
    __shared__ float sred[24];
    __shared__ bool s_last;
    int blk = blockIdx.x;
    int t   = threadIdx.x;

    if (blk < 2*CPB) {
        run_var(in, tgt, 2 + (blk >> 7), blk & 127, sh, sred, t);
    } else {
        run_dist(2 + (blk - 2*CPB), sh, sred, t);         // b = 2 or 3
    }

    __syncthreads();
    if (t == 0) {
        __threadfence();
        s_last = (atomicAdd(&g_tc, 1u) == K3BLK - 1);
    }
    __syncthreads();
    if (s_last) {
        if (t == 0) {
            float s = 0.f;
#pragma unroll
            for (int bb = 0; bb < BB; bb++) {
                float var_term  = g_var[bb]  * (1.f / (float)NI);
                float dist_term = g_dist[bb] * (1.f / (float)(NI * (NI - 1)));
                float reg_term  = g_reg[bb]  * (1.f / (float)NI);
                s += var_term + dist_term + 0.001f * reg_term;
            }
            out[0] = s * (1.f / (float)BB);
        }
        // cleanup for next graph replay (disjoint from t0's work above)
        for (int i = t; i < BB*CC*NI; i += TPB) g_sums[i] = 0.f;
        for (int i = t; i < BB*NI;    i += TPB) g_counts[i] = 0;
        __syncthreads();
        if (t < BB) g_var[t] = 0.f;
        if (t == 0) { g_ta = 0u; g_tb = 0u; g_tc = 0u; }
    }
}

extern "C" void kernel_launch(void* const* d_in, const int* in_sizes, int n_in,
                              void* d_out, int out_size) {
    const float* in  = (const float*)d_in[0];
    const int*   tgt = (const int*)d_in[1];
    float*       out = (float*)d_out;
    (void)in_sizes; (void)n_in; (void)out_size;

    k1<<<2*CPB, TPB>>>(in, tgt);
    k2<<<2*2*CPB + 2, TPB>>>(in, tgt);
    k3<<<K3BLK, TPB>>>(in, tgt, out);
}

// round 13
// speedup vs baseline: 1.4134x; 1.4134x over previous
#include <cuda_runtime.h>
#include <cuda_bf16.h>
#include <math.h>

// Problem constants (fixed by the reference setup)
#define BB 4
#define CC 32
#define NCP 16          // channel pairs
#define PP 262144       // 512*512 pixels per image
#define NI 100          // n_instances
#define CHUNK 2048      // pixels per block
#define TPB 512
#define NCOPY 8         // bank-sliced histogram copies
#define NBLK 512        // 4 batches x 128 chunks
#define NBLK2 516       // + 4 distance/reg blocks

// Scratch (no device allocation allowed -> __device__ globals).
// Zero at module load; pass2's ticket block re-zeros accumulators after each
// run so every graph replay starts clean.
__device__ float g_sums[BB*CC*NI];   // [b][c*NI+k]
__device__ int   g_counts[BB*NI];
__device__ float g_var[BB];
__device__ float g_dist[BB];         // plain-stored every run
__device__ float g_reg[BB];          // plain-stored every run
__device__ unsigned int g_t2;

// -------- Pass 1: per-label sums (bf16x2 atomics, 8-way bank-sliced) --------
__global__ __launch_bounds__(TPB) void pass1_k(const float* __restrict__ in,
                                               const int* __restrict__ tgt) {
    __shared__ __align__(16) __nv_bfloat162 ssum[NCP*NI*NCOPY]; // [(cp*100+k)*8+copy]
    __shared__ int scnt[NI];

    int blk   = blockIdx.x;
    int b     = blk >> 7;           // /128
    int chunk = blk & 127;
    int p0    = chunk * CHUNK;
    int t     = threadIdx.x;
    int cpy   = t & (NCOPY-1);

    for (int i = t; i < NCP*NI*NCOPY/8; i += TPB) {
        ((uint4*)ssum)[i*2]   = make_uint4(0,0,0,0);
        ((uint4*)ssum)[i*2+1] = make_uint4(0,0,0,0);
    }
    for (int i = t; i < NI; i += TPB) scnt[i] = 0;
    __syncthreads();

    const int4* tg = (const int4*)(tgt + (size_t)b * PP + p0);
    int4 lv = tg[t];
    int lbl[4] = {lv.x, lv.y, lv.z, lv.w};
#pragma unroll
    for (int k = 0; k < 4; k++) atomicAdd(&scnt[lbl[k]], 1);

    int s0 = lbl[0]*NCOPY + cpy;
    int s1 = lbl[1]*NCOPY + cpy;
    int s2 = lbl[2]*NCOPY + cpy;
    int s3 = lbl[3]*NCOPY + cpy;

    const float* base = in + (size_t)b * CC * PP + p0;
#pragma unroll 2
    for (int cp = 0; cp < NCP; cp++) {
        const float4* pc0 = (const float4*)(base + (size_t)(2*cp)   * PP);
        const float4* pc1 = (const float4*)(base + (size_t)(2*cp+1) * PP);
        float4 v0 = pc0[t];
        float4 v1 = pc1[t];
        __nv_bfloat162 p0v = __floats2bfloat162_rn(v0.x, v1.x);
        __nv_bfloat162 p1v = __floats2bfloat162_rn(v0.y, v1.y);
        __nv_bfloat162 p2v = __floats2bfloat162_rn(v0.z, v1.z);
        __nv_bfloat162 p3v = __floats2bfloat162_rn(v0.w, v1.w);
        int cb = cp*NI*NCOPY;
        atomicAdd(&ssum[cb + s0], p0v);
        atomicAdd(&ssum[cb + s1], p1v);
        atomicAdd(&ssum[cb + s2], p2v);
        atomicAdd(&ssum[cb + s3], p3v);
    }
    __syncthreads();

    // flush: vectorized read of the 8 copies (32B = 2 x uint4), bf16 -> fp32
    float* gs = g_sums + (size_t)b * CC * NI;
    for (int i = t; i < NCP*NI; i += TPB) {
        int cp = i / NI;
        int k  = i - cp * NI;
        uint4 a = ((const uint4*)ssum)[i*2];
        uint4 c = ((const uint4*)ssum)[i*2+1];
        float sx = 0.f, sy = 0.f;
        unsigned int w[8] = {a.x, a.y, a.z, a.w, c.x, c.y, c.z, c.w};
#pragma unroll
        for (int j = 0; j < 8; j++) {
            __nv_bfloat162 v = *(__nv_bfloat162*)&w[j];
            sx += __bfloat162float(v.x);
            sy += __bfloat162float(v.y);
        }
        atomicAdd(&gs[(2*cp)   * NI + k], sx);
        atomicAdd(&gs[(2*cp+1) * NI + k], sy);
    }
    int* gc = g_counts + b * NI;
    for (int i = t; i < NI; i += TPB) atomicAdd(&gc[i], scnt[i]);
}

// -------- Pass 2: 512 variance blocks (inline means) + 4 dist blocks + final --
__global__ __launch_bounds__(TPB) void pass2_k(const float* __restrict__ in,
                                               const int* __restrict__ tgt,
                                               float* __restrict__ out) {
    __shared__ float sh[NI*33 + NI + 32];
    __shared__ bool s_last;
    int blk = blockIdx.x;
    int t   = threadIdx.x;

    if (blk < NBLK) {
        // ---- variance term (means computed inline from g_sums) ----
        float* smean = sh;                 // [c*100+k]
        float* sinv  = sh + CC*NI;         // [k]
        float* red   = sh + CC*NI + NI;

        int b  = blk >> 7;
        int p0 = (blk & 127) * CHUNK;

        const float* gs = g_sums + (size_t)b * CC * NI;
        const int*   gc = g_counts + b * NI;
        for (int i = t; i < NI; i += TPB) {
            int cnt = gc[i];
            sinv[i] = (cnt > 0) ? 1.f / (float)cnt : 0.f;
        }
        for (int i = t; i < CC*NI; i += TPB) {
            int k = i % NI;
            int cnt = gc[k];
            smean[i] = (cnt > 0) ? gs[i] / (float)cnt : 0.f;
        }
        __syncthreads();

        const int4* tg = (const int4*)(tgt + (size_t)b * PP + p0);
        int4 lv = tg[t];
        int lbl[4] = {lv.x, lv.y, lv.z, lv.w};

        float acc[4] = {0.f, 0.f, 0.f, 0.f};
        const float* base = in + (size_t)b * CC * PP + p0;
#pragma unroll 4
        for (int c = 0; c < CC; c++) {
            const float4* pc = (const float4*)(base + (size_t)c * PP);
            float4 v = pc[t];
            float d0 = v.x - smean[c*NI + lbl[0]];
            float d1 = v.y - smean[c*NI + lbl[1]];
            float d2 = v.z - smean[c*NI + lbl[2]];
            float d3 = v.w - smean[c*NI + lbl[3]];
            acc[0] = fmaf(d0, d0, acc[0]);
            acc[1] = fmaf(d1, d1, acc[1]);
            acc[2] = fmaf(d2, d2, acc[2]);
            acc[3] = fmaf(d3, d3, acc[3]);
        }

        float local = 0.f;
#pragma unroll
        for (int k = 0; k < 4; k++) {
            float n = sqrtf(acc[k]);
            float h = fmaxf(n - 0.75f, 0.f);   // DELTA_VAR
            local += h * h * sinv[lbl[k]];
        }
#pragma unroll
        for (int o = 16; o > 0; o >>= 1) local += __shfl_down_sync(0xffffffffu, local, o);
        if ((t & 31) == 0) red[t >> 5] = local;
        __syncthreads();
        if (t < 32) {
            float v = (t < TPB/32) ? red[t] : 0.f;
#pragma unroll
            for (int o = 16; o > 0; o >>= 1) v += __shfl_down_sync(0xffffffffu, v, o);
            if (t == 0) atomicAdd(&g_var[b], v);
        }
    } else {
        // ---- distance + reg terms (one batch per block, smem-only) ----
        float* sm = sh;                    // [k*33+c] padded
        int b = blk - NBLK;

        const float* gs = g_sums + (size_t)b * CC * NI;
        const int*   gc = g_counts + b * NI;
        for (int i = t; i < CC*NI; i += TPB) {
            int c = i / NI;
            int k = i - c * NI;
            int cnt = gc[k];
            sm[k*33 + c] = (cnt > 0) ? gs[i] / (float)cnt : 0.f;
        }
        if (t == 0) sh[NI*33 + NI] = 0.f;   // reg accumulator
        __syncthreads();

        if (t < NI) {
            float s = 0.f;
#pragma unroll
            for (int c = 0; c < CC; c++) { float m = sm[t*33 + c]; s = fmaf(m, m, s); }
            atomicAdd(&sh[NI*33 + NI], sqrtf(s));
        }

        float local = 0.f;
        for (int idx = t; idx < NI*NI; idx += TPB) {
            int i = idx / NI;
            int j = idx - i * NI;
            if (i != j) {
                float d2 = 0.f;
#pragma unroll
                for (int c = 0; c < CC; c++) {
                    float d = sm[i*33 + c] - sm[j*33 + c];
                    d2 = fmaf(d, d, d2);
                }
                float d = (d2 > 0.f) ? sqrtf(d2) : 1.f;   // jnp.where(d2>0, d2, 1)
                float h = fmaxf(4.f - d, 0.f);            // 2*DELTA_DIST
                local += h * h;
            }
        }
        float* red = sh + NI*33;
#pragma unroll
        for (int o = 16; o > 0; o >>= 1) local += __shfl_down_sync(0xffffffffu, local, o);
        if ((t & 31) == 0) red[t >> 5] = local;
        __syncthreads();
        if (t < 32) {
            float v = (t < TPB/32) ? red[t] : 0.f;
#pragma unroll
            for (int o = 16; o > 0; o >>= 1) v += __shfl_down_sync(0xffffffffu, v, o);
            if (t == 0) {
                g_dist[b] = v;
                g_reg[b]  = sh[NI*33 + NI];
            }
        }
    }

    // ---- ticket: last block -> final combine + replay cleanup ----
    __syncthreads();
    if (t == 0) {
        __threadfence();
        unsigned r = atomicAdd(&g_t2, 1u);
        s_last = (r == NBLK2 - 1);
    }
    __syncthreads();
    if (s_last) {
        if (t == 0) {
            float s = 0.f;
#pragma unroll
            for (int bb = 0; bb < BB; bb++) {
                float var_term  = g_var[bb]  * (1.f / (float)NI);
                float dist_term = g_dist[bb] * (1.f / (float)(NI * (NI - 1)));
                float reg_term  = g_reg[bb]  * (1.f / (float)NI);
                s += var_term + dist_term + 0.001f * reg_term;
            }
            out[0] = s * (1.f / (float)BB);
        }
        // cleanup for next graph replay (disjoint from t0's work above)
        for (int i = t; i < BB*CC*NI; i += TPB) g_sums[i] = 0.f;
        for (int i = t; i < BB*NI;    i += TPB) g_counts[i] = 0;
        __syncthreads();
        if (t < BB) g_var[t] = 0.f;
        if (t == 0) g_t2 = 0u;
    }
}

extern "C" void kernel_launch(void* const* d_in, const int* in_sizes, int n_in,
                              void* d_out, int out_size) {
    const float* in  = (const float*)d_in[0];
    const int*   tgt = (const int*)d_in[1];
    float*       out = (float*)d_out;
    (void)in_sizes; (void)n_in; (void)out_size;

    pass1_k<<<NBLK, TPB>>>(in, tgt);
    pass2_k<<<NBLK2, TPB>>>(in, tgt, out);
}

// round 14
// speedup vs baseline: 1.5055x; 1.0652x over previous
#include <cuda_runtime.h>
#include <cuda_bf16.h>
#include <math.h>

// Problem constants (fixed by the reference setup)
#define BB 4
#define CC 32
#define NCP 16          // channel pairs
#define PP 262144       // 512*512 pixels per image
#define NI 100          // n_instances
#define CHUNK 2048      // pixels per block
#define TPB 512
#define NCOPY 8         // bank-sliced histogram copies
#define NBLK 512        // 4 batches x 128 chunks
#define NDIST 8         // distance blocks: 2 per batch
#define NBLK2 (NBLK + NDIST)   // 520

// Scratch (no device allocation allowed -> __device__ globals).
// Zero at module load; pass2's ticket block re-zeros accumulators after each
// run so every graph replay starts clean.
__device__ float g_sums[BB*CC*NI];   // [b][c*NI+k]
__device__ int   g_counts[BB*NI];
__device__ float g_var[BB];
__device__ float g_dist[BB];         // atomically accumulated every run
__device__ float g_reg[BB];          // plain-stored every run
__device__ unsigned int g_t2;

// -------- Pass 1: per-label sums (bf16x2 atomics, 8-way bank-sliced) --------
__global__ __launch_bounds__(TPB) void pass1_k(const float* __restrict__ in,
                                               const int* __restrict__ tgt) {
    __shared__ __align__(16) __nv_bfloat162 ssum[NCP*NI*NCOPY]; // [(cp*100+k)*8+copy]
    __shared__ int scnt[NI];

    int blk   = blockIdx.x;
    int b     = blk >> 7;           // /128
    int chunk = blk & 127;
    int p0    = chunk * CHUNK;
    int t     = threadIdx.x;
    int cpy   = t & (NCOPY-1);

    for (int i = t; i < NCP*NI*NCOPY/8; i += TPB) {
        ((uint4*)ssum)[i*2]   = make_uint4(0,0,0,0);
        ((uint4*)ssum)[i*2+1] = make_uint4(0,0,0,0);
    }
    for (int i = t; i < NI; i += TPB) scnt[i] = 0;
    __syncthreads();

    const int4* tg = (const int4*)(tgt + (size_t)b * PP + p0);
    int4 lv = tg[t];
    int lbl[4] = {lv.x, lv.y, lv.z, lv.w};
#pragma unroll
    for (int k = 0; k < 4; k++) atomicAdd(&scnt[lbl[k]], 1);

    int s0 = lbl[0]*NCOPY + cpy;
    int s1 = lbl[1]*NCOPY + cpy;
    int s2 = lbl[2]*NCOPY + cpy;
    int s3 = lbl[3]*NCOPY + cpy;

    const float* base = in + (size_t)b * CC * PP + p0;
#pragma unroll 2
    for (int cp = 0; cp < NCP; cp++) {
        const float4* pc0 = (const float4*)(base + (size_t)(2*cp)   * PP);
        const float4* pc1 = (const float4*)(base + (size_t)(2*cp+1) * PP);
        float4 v0 = pc0[t];
        float4 v1 = pc1[t];
        __nv_bfloat162 p0v = __floats2bfloat162_rn(v0.x, v1.x);
        __nv_bfloat162 p1v = __floats2bfloat162_rn(v0.y, v1.y);
        __nv_bfloat162 p2v = __floats2bfloat162_rn(v0.z, v1.z);
        __nv_bfloat162 p3v = __floats2bfloat162_rn(v0.w, v1.w);
        int cb = cp*NI*NCOPY;
        atomicAdd(&ssum[cb + s0], p0v);
        atomicAdd(&ssum[cb + s1], p1v);
        atomicAdd(&ssum[cb + s2], p2v);
        atomicAdd(&ssum[cb + s3], p3v);
    }
    __syncthreads();

    // flush: vectorized read of the 8 copies (32B = 2 x uint4), bf16 -> fp32
    float* gs = g_sums + (size_t)b * CC * NI;
    for (int i = t; i < NCP*NI; i += TPB) {
        int cp = i / NI;
        int k  = i - cp * NI;
        uint4 a = ((const uint4*)ssum)[i*2];
        uint4 c = ((const uint4*)ssum)[i*2+1];
        float sx = 0.f, sy = 0.f;
        unsigned int w[8] = {a.x, a.y, a.z, a.w, c.x, c.y, c.z, c.w};
#pragma unroll
        for (int j = 0; j < 8; j++) {
            __nv_bfloat162 v = *(__nv_bfloat162*)&w[j];
            sx += __bfloat162float(v.x);
            sy += __bfloat162float(v.y);
        }
        atomicAdd(&gs[(2*cp)   * NI + k], sx);
        atomicAdd(&gs[(2*cp+1) * NI + k], sy);
    }
    int* gc = g_counts + b * NI;
    for (int i = t; i < NI; i += TPB) atomicAdd(&gc[i], scnt[i]);
}

// -------- Pass 2: 512 variance blocks (inline means) + 8 dist blocks + final --
__global__ __launch_bounds__(TPB) void pass2_k(const float* __restrict__ in,
                                               const int* __restrict__ tgt,
                                               float* __restrict__ out) {
    __shared__ float sh[NI*33 + NI + 32];
    __shared__ bool s_last;
    int blk = blockIdx.x;
    int t   = threadIdx.x;

    if (blk < NBLK) {
        // ---- variance term (means = sums * inv_count, no divides) ----
        float* smean = sh;                 // [c*100+k]
        float* sinv  = sh + CC*NI;         // [k]
        float* red   = sh + CC*NI + NI;

        int b  = blk >> 7;
        int p0 = (blk & 127) * CHUNK;

        const float* gs = g_sums + (size_t)b * CC * NI;
        const int*   gc = g_counts + b * NI;
        for (int i = t; i < NI; i += TPB) {
            int cnt = gc[i];
            sinv[i] = (cnt > 0) ? __frcp_rn((float)cnt) : 0.f;
        }
        __syncthreads();
        for (int i = t; i < CC*NI; i += TPB) {
            int k = i % NI;
            smean[i] = gs[i] * sinv[k];
        }
        __syncthreads();

        const int4* tg = (const int4*)(tgt + (size_t)b * PP + p0);
        int4 lv = tg[t];
        int lbl[4] = {lv.x, lv.y, lv.z, lv.w};

        float acc[4] = {0.f, 0.f, 0.f, 0.f};
        const float* base = in + (size_t)b * CC * PP + p0;
#pragma unroll 4
        for (int c = 0; c < CC; c++) {
            const float4* pc = (const float4*)(base + (size_t)c * PP);
            float4 v = pc[t];
            float d0 = v.x - smean[c*NI + lbl[0]];
            float d1 = v.y - smean[c*NI + lbl[1]];
            float d2 = v.z - smean[c*NI + lbl[2]];
            float d3 = v.w - smean[c*NI + lbl[3]];
            acc[0] = fmaf(d0, d0, acc[0]);
            acc[1] = fmaf(d1, d1, acc[1]);
            acc[2] = fmaf(d2, d2, acc[2]);
            acc[3] = fmaf(d3, d3, acc[3]);
        }

        float local = 0.f;
#pragma unroll
        for (int k = 0; k < 4; k++) {
            float n = sqrtf(acc[k]);
            float h = fmaxf(n - 0.75f, 0.f);   // DELTA_VAR
            local += h * h * sinv[lbl[k]];
        }
#pragma unroll
        for (int o = 16; o > 0; o >>= 1) local += __shfl_down_sync(0xffffffffu, local, o);
        if ((t & 31) == 0) red[t >> 5] = local;
        __syncthreads();
        if (t < 32) {
            float v = (t < TPB/32) ? red[t] : 0.f;
#pragma unroll
            for (int o = 16; o > 0; o >>= 1) v += __shfl_down_sync(0xffffffffu, v, o);
            if (t == 0) atomicAdd(&g_var[b], v);
        }
    } else {
        // ---- distance + reg terms: 2 blocks per batch (i-range halves) ----
        float* sm   = sh;                  // [k*33+c] padded
        float* sinv = sh + NI*33;          // reuse region: [k] inv counts? not needed
        int d    = blk - NBLK;
        int b    = d >> 1;
        int half = d & 1;

        const float* gs = g_sums + (size_t)b * CC * NI;
        const int*   gc = g_counts + b * NI;
        // inv counts into registers via small smem staging
        if (t < NI) {
            int cnt = gc[t];
            sinv[t] = (cnt > 0) ? __frcp_rn((float)cnt) : 0.f;
        }
        __syncthreads();
        for (int i = t; i < CC*NI; i += TPB) {
            int c = i / NI;
            int k = i - c * NI;
            sm[k*33 + c] = gs[i] * sinv[k];
        }
        if (t == 0) sh[NI*33 + NI] = 0.f;   // reg accumulator
        __syncthreads();

        // reg term (first half-block only)
        if (half == 0 && t < NI) {
            float s = 0.f;
#pragma unroll
            for (int c = 0; c < CC; c++) { float m = sm[t*33 + c]; s = fmaf(m, m, s); }
            atomicAdd(&sh[NI*33 + NI], sqrtf(s));
        }

        // distance term: this block handles pair-indices [half*5000, half*5000+5000)
        float local = 0.f;
        for (int idx = half*5000 + t; idx < half*5000 + 5000; idx += TPB) {
            int i = idx / NI;
            int j = idx - i * NI;
            if (i != j) {
                float d2 = 0.f;
#pragma unroll
                for (int c = 0; c < CC; c++) {
                    float dd = sm[i*33 + c] - sm[j*33 + c];
                    d2 = fmaf(dd, dd, d2);
                }
                float dist = (d2 > 0.f) ? sqrtf(d2) : 1.f;   // jnp.where(d2>0, d2, 1)
                float h = fmaxf(4.f - dist, 0.f);            // 2*DELTA_DIST
                local += h * h;
            }
        }
        float* red = sh + NI*33 + NI + 1;
#pragma unroll
        for (int o = 16; o > 0; o >>= 1) local += __shfl_down_sync(0xffffffffu, local, o);
        if ((t & 31) == 0) red[t >> 5] = local;
        __syncthreads();
        if (t < 32) {
            float v = (t < TPB/32) ? red[t] : 0.f;
#pragma unroll
            for (int o = 16; o > 0; o >>= 1) v += __shfl_down_sync(0xffffffffu, v, o);
            if (t == 0) {
                atomicAdd(&g_dist[b], v);
                if (half == 0) g_reg[b] = sh[NI*33 + NI];
            }
        }
    }

    // ---- ticket: last block -> final combine + replay cleanup ----
    __syncthreads();
    if (t == 0) {
        __threadfence();
        unsigned r = atomicAdd(&g_t2, 1u);
        s_last = (r == NBLK2 - 1);
    }
    __syncthreads();
    if (s_last) {
        if (t == 0) {
            float s = 0.f;
#pragma unroll
            for (int bb = 0; bb < BB; bb++) {
                float var_term  = g_var[bb]  * (1.f / (float)NI);
                float dist_term = g_dist[bb] * (1.f / (float)(NI * (NI - 1)));
                float reg_term  = g_reg[bb]  * (1.f / (float)NI);
                s += var_term + dist_term + 0.001f * reg_term;
            }
            out[0] = s * (1.f / (float)BB);
        }
        // cleanup for next graph replay (disjoint from t0's work above)
        for (int i = t; i < BB*CC*NI; i += TPB) g_sums[i] = 0.f;
        for (int i = t; i < BB*NI;    i += TPB) g_counts[i] = 0;
        __syncthreads();
        if (t < BB) { g_var[t] = 0.f; g_dist[t] = 0.f; }
        if (t == 0) g_t2 = 0u;
    }
}

extern "C" void kernel_launch(void* const* d_in, const int* in_sizes, int n_in,
                              void* d_out, int out_size) {
    const float* in  = (const float*)d_in[0];
    const int*   tgt = (const int*)d_in[1];
    float*       out = (float*)d_out;
    (void)in_sizes; (void)n_in; (void)out_size;

    pass1_k<<<NBLK, TPB>>>(in, tgt);
    pass2_k<<<NBLK2, TPB>>>(in, tgt, out);
}

// round 15
// speedup vs baseline: 1.5409x; 1.0235x over previous
#include <cuda_runtime.h>
#include <cuda_bf16.h>
#include <math.h>

// Problem constants (fixed by the reference setup)
#define BB 4
#define CC 32
#define NCP 16          // channel pairs
#define PP 262144       // 512*512 pixels per image
#define NI 100          // n_instances
#define CHUNK 2048      // pixels per block
#define TPB 512
#define NCOPY 8         // bank-sliced histogram copies
#define NBLK 512        // 4 batches x 128 chunks
#define NDIST 8         // distance blocks: 2 per batch
#define NBLK2 (NBLK + NDIST)   // 520

// Scratch (no device allocation allowed -> __device__ globals).
// Zero at module load; pass2's ticket block re-zeros accumulators after each
// run so every graph replay starts clean.
__device__ float g_sums[BB*CC*NI];   // [b][c*NI+k]
__device__ int   g_counts[BB*NI];
__device__ float g_var[BB];
__device__ float g_dist[BB];         // atomically accumulated every run
__device__ float g_reg[BB];          // plain-stored every run
__device__ unsigned int g_t2;

// -------- Pass 1: per-label sums (bf16x2 atomics, 8-way bank-sliced) --------
__global__ __launch_bounds__(TPB) void pass1_k(const float* __restrict__ in,
                                               const int* __restrict__ tgt) {
    __shared__ __align__(16) __nv_bfloat162 ssum[NCP*NI*NCOPY]; // [(cp*100+k)*8+copy]
    __shared__ int scnt[NI];

    int blk   = blockIdx.x;
    int b     = blk >> 7;           // /128
    int chunk = blk & 127;
    int p0    = chunk * CHUNK;
    int t     = threadIdx.x;
    int cpy   = t & (NCOPY-1);

    for (int i = t; i < NCP*NI*NCOPY/8; i += TPB) {
        ((uint4*)ssum)[i*2]   = make_uint4(0,0,0,0);
        ((uint4*)ssum)[i*2+1] = make_uint4(0,0,0,0);
    }
    for (int i = t; i < NI; i += TPB) scnt[i] = 0;
    __syncthreads();

    const int4* tg = (const int4*)(tgt + (size_t)b * PP + p0);
    int4 lv = tg[t];
    int lbl[4] = {lv.x, lv.y, lv.z, lv.w};
#pragma unroll
    for (int k = 0; k < 4; k++) atomicAdd(&scnt[lbl[k]], 1);

    int s0 = lbl[0]*NCOPY + cpy;
    int s1 = lbl[1]*NCOPY + cpy;
    int s2 = lbl[2]*NCOPY + cpy;
    int s3 = lbl[3]*NCOPY + cpy;

    const float* base = in + (size_t)b * CC * PP + p0;
#pragma unroll 2
    for (int cp = 0; cp < NCP; cp++) {
        const float4* pc0 = (const float4*)(base + (size_t)(2*cp)   * PP);
        const float4* pc1 = (const float4*)(base + (size_t)(2*cp+1) * PP);
        float4 v0 = pc0[t];
        float4 v1 = pc1[t];
        __nv_bfloat162 p0v = __floats2bfloat162_rn(v0.x, v1.x);
        __nv_bfloat162 p1v = __floats2bfloat162_rn(v0.y, v1.y);
        __nv_bfloat162 p2v = __floats2bfloat162_rn(v0.z, v1.z);
        __nv_bfloat162 p3v = __floats2bfloat162_rn(v0.w, v1.w);
        int cb = cp*NI*NCOPY;
        atomicAdd(&ssum[cb + s0], p0v);
        atomicAdd(&ssum[cb + s1], p1v);
        atomicAdd(&ssum[cb + s2], p2v);
        atomicAdd(&ssum[cb + s3], p3v);
    }
    __syncthreads();

    // flush: vectorized read of the 8 copies (32B = 2 x uint4), bf16 -> fp32
    float* gs = g_sums + (size_t)b * CC * NI;
    for (int i = t; i < NCP*NI; i += TPB) {
        int cp = i / NI;
        int k  = i - cp * NI;
        uint4 a = ((const uint4*)ssum)[i*2];
        uint4 c = ((const uint4*)ssum)[i*2+1];
        float sx = 0.f, sy = 0.f;
        unsigned int w[8] = {a.x, a.y, a.z, a.w, c.x, c.y, c.z, c.w};
#pragma unroll
        for (int j = 0; j < 8; j++) {
            __nv_bfloat162 v = *(__nv_bfloat162*)&w[j];
            sx += __bfloat162float(v.x);
            sy += __bfloat162float(v.y);
        }
        atomicAdd(&gs[(2*cp)   * NI + k], sx);
        atomicAdd(&gs[(2*cp+1) * NI + k], sy);
    }
    int* gc = g_counts + b * NI;
    for (int i = t; i < NI; i += TPB) atomicAdd(&gc[i], scnt[i]);
}

// -------- Pass 2: 512 variance blocks (bf16x2 packed means) + 8 dist + final --
__global__ __launch_bounds__(TPB) void pass2_k(const float* __restrict__ in,
                                               const int* __restrict__ tgt,
                                               float* __restrict__ out) {
    __shared__ float sh[NI*33 + NI + 32];
    __shared__ bool s_last;
    int blk = blockIdx.x;
    int t   = threadIdx.x;

    if (blk < NBLK) {
        // ---- variance term: means packed bf16x2 by channel pair ----
        __nv_bfloat162* smean2 = (__nv_bfloat162*)sh;      // [cp*100+k], 1600
        float* sinv = sh + NCP*NI;                         // [k]
        float* red  = sh + NCP*NI + NI;

        int b  = blk >> 7;
        int p0 = (blk & 127) * CHUNK;

        const float* gs = g_sums + (size_t)b * CC * NI;
        const int*   gc = g_counts + b * NI;
        for (int i = t; i < NI; i += TPB) {
            int cnt = gc[i];
            sinv[i] = (cnt > 0) ? __frcp_rn((float)cnt) : 0.f;
        }
        __syncthreads();
        for (int i = t; i < NCP*NI; i += TPB) {
            int cp = i / NI;
            int k  = i - cp * NI;
            float iv = sinv[k];
            float mx = gs[(2*cp)   * NI + k] * iv;
            float my = gs[(2*cp+1) * NI + k] * iv;
            smean2[i] = __floats2bfloat162_rn(mx, my);
        }
        __syncthreads();

        const int4* tg = (const int4*)(tgt + (size_t)b * PP + p0);
        int4 lv = tg[t];
        int lbl[4] = {lv.x, lv.y, lv.z, lv.w};

        float acc[4] = {0.f, 0.f, 0.f, 0.f};
        const float* base = in + (size_t)b * CC * PP + p0;
#pragma unroll 4
        for (int cp = 0; cp < NCP; cp++) {
            const float4* pc0 = (const float4*)(base + (size_t)(2*cp)   * PP);
            const float4* pc1 = (const float4*)(base + (size_t)(2*cp+1) * PP);
            float4 v0 = pc0[t];
            float4 v1 = pc1[t];
            int cb = cp*NI;
            __nv_bfloat162 m0 = smean2[cb + lbl[0]];
            __nv_bfloat162 m1 = smean2[cb + lbl[1]];
            __nv_bfloat162 m2 = smean2[cb + lbl[2]];
            __nv_bfloat162 m3 = smean2[cb + lbl[3]];
            float d0a = v0.x - __bfloat162float(m0.x);
            float d0b = v1.x - __bfloat162float(m0.y);
            float d1a = v0.y - __bfloat162float(m1.x);
            float d1b = v1.y - __bfloat162float(m1.y);
            float d2a = v0.z - __bfloat162float(m2.x);
            float d2b = v1.z - __bfloat162float(m2.y);
            float d3a = v0.w - __bfloat162float(m3.x);
            float d3b = v1.w - __bfloat162float(m3.y);
            acc[0] = fmaf(d0a, d0a, acc[0]); acc[0] = fmaf(d0b, d0b, acc[0]);
            acc[1] = fmaf(d1a, d1a, acc[1]); acc[1] = fmaf(d1b, d1b, acc[1]);
            acc[2] = fmaf(d2a, d2a, acc[2]); acc[2] = fmaf(d2b, d2b, acc[2]);
            acc[3] = fmaf(d3a, d3a, acc[3]); acc[3] = fmaf(d3b, d3b, acc[3]);
        }

        float local = 0.f;
#pragma unroll
        for (int k = 0; k < 4; k++) {
            float n = sqrtf(acc[k]);
            float h = fmaxf(n - 0.75f, 0.f);   // DELTA_VAR
            local += h * h * sinv[lbl[k]];
        }
#pragma unroll
        for (int o = 16; o > 0; o >>= 1) local += __shfl_down_sync(0xffffffffu, local, o);
        if ((t & 31) == 0) red[t >> 5] = local;
        __syncthreads();
        if (t < 32) {
            float v = (t < TPB/32) ? red[t] : 0.f;
#pragma unroll
            for (int o = 16; o > 0; o >>= 1) v += __shfl_down_sync(0xffffffffu, v, o);
            if (t == 0) atomicAdd(&g_var[b], v);
        }
    } else {
        // ---- distance + reg terms: 2 blocks per batch (fp32 means) ----
        float* sm   = sh;                  // [k*33+c] padded
        float* sinv = sh + NI*33;
        int d    = blk - NBLK;
        int b    = d >> 1;
        int half = d & 1;

        const float* gs = g_sums + (size_t)b * CC * NI;
        const int*   gc = g_counts + b * NI;
        if (t < NI) {
            int cnt = gc[t];
            sinv[t] = (cnt > 0) ? __frcp_rn((float)cnt) : 0.f;
        }
        __syncthreads();
        for (int i = t; i < CC*NI; i += TPB) {
            int c = i / NI;
            int k = i - c * NI;
            sm[k*33 + c] = gs[i] * sinv[k];
        }
        if (t == 0) sh[NI*33 + NI] = 0.f;   // reg accumulator
        __syncthreads();

        // reg term (first half-block only)
        if (half == 0 && t < NI) {
            float s = 0.f;
#pragma unroll
            for (int c = 0; c < CC; c++) { float m = sm[t*33 + c]; s = fmaf(m, m, s); }
            atomicAdd(&sh[NI*33 + NI], sqrtf(s));
        }

        // distance term: this block handles pair-indices [half*5000, half*5000+5000)
        float local = 0.f;
        for (int idx = half*5000 + t; idx < half*5000 + 5000; idx += TPB) {
            int i = idx / NI;
            int j = idx - i * NI;
            if (i != j) {
                float d2 = 0.f;
#pragma unroll
                for (int c = 0; c < CC; c++) {
                    float dd = sm[i*33 + c] - sm[j*33 + c];
                    d2 = fmaf(dd, dd, d2);
                }
                float dist = (d2 > 0.f) ? sqrtf(d2) : 1.f;   // jnp.where(d2>0, d2, 1)
                float h = fmaxf(4.f - dist, 0.f);            // 2*DELTA_DIST
                local += h * h;
            }
        }
        float* red = sh + NI*33 + NI + 1;
#pragma unroll
        for (int o = 16; o > 0; o >>= 1) local += __shfl_down_sync(0xffffffffu, local, o);
        if ((t & 31) == 0) red[t >> 5] = local;
        __syncthreads();
        if (t < 32) {
            float v = (t < TPB/32) ? red[t] : 0.f;
#pragma unroll
            for (int o = 16; o > 0; o >>= 1) v += __shfl_down_sync(0xffffffffu, v, o);
            if (t == 0) {
                atomicAdd(&g_dist[b], v);
                if (half == 0) g_reg[b] = sh[NI*33 + NI];
            }
        }
    }

    // ---- ticket: last block -> final combine + replay cleanup ----
    __syncthreads();
    if (t == 0) {
        __threadfence();
        unsigned r = atomicAdd(&g_t2, 1u);
        s_last = (r == NBLK2 - 1);
    }
    __syncthreads();
    if (s_last) {
        if (t == 0) {
            float s = 0.f;
#pragma unroll
            for (int bb = 0; bb < BB; bb++) {
                float var_term  = g_var[bb]  * (1.f / (float)NI);
                float dist_term = g_dist[bb] * (1.f / (float)(NI * (NI - 1)));
                float reg_term  = g_reg[bb]  * (1.f / (float)NI);
                s += var_term + dist_term + 0.001f * reg_term;
            }
            out[0] = s * (1.f / (float)BB);
        }
        // cleanup for next graph replay (disjoint from t0's work above)
        for (int i = t; i < BB*CC*NI; i += TPB) g_sums[i] = 0.f;
        for (int i = t; i < BB*NI;    i += TPB) g_counts[i] = 0;
        __syncthreads();
        if (t < BB) { g_var[t] = 0.f; g_dist[t] = 0.f; }
        if (t == 0) g_t2 = 0u;
    }
}

extern "C" void kernel_launch(void* const* d_in, const int* in_sizes, int n_in,
                              void* d_out, int out_size) {
    const float* in  = (const float*)d_in[0];
    const int*   tgt = (const int*)d_in[1];
    float*       out = (float*)d_out;
    (void)in_sizes; (void)n_in; (void)out_size;

    pass1_k<<<NBLK, TPB>>>(in, tgt);
    pass2_k<<<NBLK2, TPB>>>(in, tgt, out);
}